// round 3
// baseline (speedup 1.0000x reference)
#include <cuda_runtime.h>
#include <cuda_bf16.h>

#define Bb   16
#define Nn   8
#define Tt   65536
#define CPB  32            // chunks per batch
#define TPB  128
#define NVALS 80           // 64 gram + 8 sum(x^2) + 8 sum(y^2)
#define ITERS ((Tt / CPB) / 4 / TPB)   // = 4 float4 iterations per thread
#define GRID (Bb * CPB)

// Deterministic scratch for per-chunk partial sums (no float atomics anywhere).
__device__ float g_partial[GRID * NVALS];
__device__ unsigned int g_count = 0;

__device__ __forceinline__ float dot4(float4 a, float4 b) {
    return a.x * b.x + a.y * b.y + a.z * b.z + a.w * b.w;
}

// ---------------------------------------------------------------------------
// Fused kernel.
// Phase 1 (all 512 blocks): streaming Gram + self-norms; every input byte
//   read exactly once; per-(block,value) partials to g_partial. (~L2-BW bound)
// Phase 2 (last finishing block only): reduce partials, linear-domain
//   Sinkhorn (thread-per-(batch,row), shfl-butterfly column sums, no exp/log
//   in the loop), loss + argmax. Deterministic: result independent of which
//   block runs the tail; counter reset each launch for graph replay.
// ---------------------------------------------------------------------------
__global__ __launch_bounds__(TPB) void k_fused(const float* __restrict__ inp,
                                               const float* __restrict__ tgt,
                                               float* __restrict__ out,
                                               int out_size) {
    const int bb  = blockIdx.x / CPB;   // batch
    const int c   = blockIdx.x % CPB;   // chunk
    const int tid = threadIdx.x;

    // ---------------- Phase 1: Gram partials ----------------
    {
        const float4* ip = reinterpret_cast<const float4*>(inp) + (size_t)bb * Nn * (Tt / 4);
        const float4* tp = reinterpret_cast<const float4*>(tgt) + (size_t)bb * Nn * (Tt / 4);
        const int base = c * (Tt / CPB / 4) + tid;

        float acc[NVALS];
#pragma unroll
        for (int v = 0; v < NVALS; v++) acc[v] = 0.f;

#pragma unroll
        for (int k = 0; k < ITERS; k++) {
            const int idx = base + k * TPB;
            float4 av[Nn], bv[Nn];
#pragma unroll
            for (int i = 0; i < Nn; i++) av[i] = ip[i * (Tt / 4) + idx];
#pragma unroll
            for (int j = 0; j < Nn; j++) bv[j] = tp[j * (Tt / 4) + idx];
#pragma unroll
            for (int i = 0; i < Nn; i++) acc[64 + i] += dot4(av[i], av[i]);
#pragma unroll
            for (int j = 0; j < Nn; j++) acc[72 + j] += dot4(bv[j], bv[j]);
#pragma unroll
            for (int i = 0; i < Nn; i++)
#pragma unroll
                for (int j = 0; j < Nn; j++)
                    acc[i * 8 + j] += dot4(av[i], bv[j]);
        }

        __shared__ float sm[TPB / 32][NVALS];
        const int lane = tid & 31, warp = tid >> 5;
#pragma unroll
        for (int v = 0; v < NVALS; v++) {
            float x = acc[v];
#pragma unroll
            for (int off = 16; off; off >>= 1) x += __shfl_down_sync(0xffffffffu, x, off);
            if (lane == 0) sm[warp][v] = x;
        }
        __syncthreads();
        if (tid < NVALS) {
            float s = 0.f;
#pragma unroll
            for (int w = 0; w < TPB / 32; w++) s += sm[w][tid];
            g_partial[blockIdx.x * NVALS + tid] = s;
        }
    }

    // ---------------- Last-block election ----------------
    __shared__ int is_last;
    __syncthreads();
    if (tid == 0) {
        __threadfence();                               // publish partials
        unsigned int prev = atomicAdd(&g_count, 1u);
        is_last = (prev == GRID - 1);
        if (is_last) g_count = 0;                      // reset for next replay
    }
    __syncthreads();
    if (!is_last) return;
    __threadfence();

    // ---------------- Phase 2: reduce + Sinkhorn ----------------
    __shared__ float G[Bb][NVALS];
    __shared__ float bloss[Bb];

    for (int v = tid; v < Bb * NVALS; v += TPB) {
        const int b = v / NVALS, k = v % NVALS;
        const float* p = &g_partial[b * CPB * NVALS + k];
        float s = 0.f;
#pragma unroll
        for (int cc = 0; cc < CPB; cc++) s += p[cc * NVALS];
        G[b][k] = s;
    }
    __syncthreads();

    const int b = tid >> 3;             // batch (16)
    const int i = tid & 7;              // row   (8)
    const float invT = 1.0f / (float)Tt;

    float L[Nn], P[Nn];
    const float sx = G[b][64 + i];
#pragma unroll
    for (int j = 0; j < Nn; j++) {
        L[j] = (sx + G[b][72 + j] - 2.f * G[b][i * 8 + j]) * invT;
        P[j] = __expf(-L[j]);           // P = exp(Z0), Z0 = -COLDNESS*L
    }

    // 10 Sinkhorn iterations in linear domain: col-normalize then row-normalize.
    // Column sums via 3-level butterfly over the 8 lanes of this batch group.
#pragma unroll
    for (int it = 0; it < 10; it++) {
        float cs[Nn];
#pragma unroll
        for (int j = 0; j < Nn; j++) cs[j] = P[j];
#pragma unroll
        for (int off = 1; off <= 4; off <<= 1)
#pragma unroll
            for (int j = 0; j < Nn; j++)
                cs[j] += __shfl_xor_sync(0xffffffffu, cs[j], off);
#pragma unroll
        for (int j = 0; j < Nn; j++) P[j] *= __fdividef(1.f, cs[j]);

        float rs = 0.f;
#pragma unroll
        for (int j = 0; j < Nn; j++) rs += P[j];
        const float rr = __fdividef(1.f, rs);
#pragma unroll
        for (int j = 0; j < Nn; j++) P[j] *= rr;
    }

    // Loss: sum_j (L + ln P) * P per row; argmax_j P (first occurrence).
    float lp = 0.f;
    int best = 0;
    float bv = P[0];
#pragma unroll
    for (int j = 0; j < Nn; j++) {
        lp += (L[j] + __logf(P[j])) * P[j];
        if (P[j] > bv) { bv = P[j]; best = j; }
    }
#pragma unroll
    for (int off = 1; off <= 4; off <<= 1)
        lp += __shfl_xor_sync(0xffffffffu, lp, off);
    if (i == 0) bloss[b] = lp;

    if (out_size >= 1 + Bb * Nn) out[1 + b * Nn + i] = (float)best;

    __syncthreads();
    if (tid == 0) {
        float s = 0.f;
#pragma unroll
        for (int k = 0; k < Bb; k++) s += bloss[k];
        out[0] = s * (1.0f / (float)Bb);
    }
}

// ---------------------------------------------------------------------------
extern "C" void kernel_launch(void* const* d_in, const int* in_sizes, int n_in,
                              void* d_out, int out_size) {
    const float* inp = (const float*)d_in[0];
    const float* tgt = (const float*)d_in[1];
    k_fused<<<GRID, TPB>>>(inp, tgt, (float*)d_out, out_size);
}

// round 4
// speedup vs baseline: 1.1381x; 1.1381x over previous
#include <cuda_runtime.h>
#include <cuda_bf16.h>

#define Bb   16
#define Nn   8
#define Tt   65536
#define CPB  32            // chunks per batch
#define TPB  128
#define NVALS 80           // 64 gram + 8 sum(x^2) + 8 sum(y^2)
#define ITERS ((Tt / CPB) / 4 / TPB)   // = 4 float4 iterations per thread
#define GRID (Bb * CPB)

// Partial sums laid out [batch][value][chunk] so k_sink reduces over a
// contiguous 128B line per output. No atomics anywhere -> deterministic.
__device__ float g_partial[Bb * NVALS * CPB];

__device__ __forceinline__ float dot4(float4 a, float4 b) {
    return a.x * b.x + a.y * b.y + a.z * b.z + a.w * b.w;
}

// ---------------------------------------------------------------------------
// Kernel 1: streaming Gram + self-norms. Register-pressure-aware inner loop:
// batch-load the 8 target float4s, then sweep input rows one at a time.
// Peak live ~125-150 regs; launch_bounds(128,3) gives ptxas a 170-reg budget
// so nothing spills (R3's 142-reg allocation spilled the accumulators).
// ---------------------------------------------------------------------------
__global__ __launch_bounds__(TPB, 3) void k_gram(const float* __restrict__ inp,
                                                 const float* __restrict__ tgt) {
    const int b   = blockIdx.x / CPB;
    const int c   = blockIdx.x % CPB;
    const int tid = threadIdx.x;

    const float4* ip = reinterpret_cast<const float4*>(inp) + (size_t)b * Nn * (Tt / 4);
    const float4* tp = reinterpret_cast<const float4*>(tgt) + (size_t)b * Nn * (Tt / 4);
    const int base = c * (Tt / CPB / 4) + tid;

    float acc[NVALS];
#pragma unroll
    for (int v = 0; v < NVALS; v++) acc[v] = 0.f;

#pragma unroll
    for (int k = 0; k < ITERS; k++) {
        const int idx = base + k * TPB;

        float4 bv[Nn];
#pragma unroll
        for (int j = 0; j < Nn; j++) bv[j] = tp[j * (Tt / 4) + idx];
#pragma unroll
        for (int j = 0; j < Nn; j++) acc[72 + j] += dot4(bv[j], bv[j]);

#pragma unroll
        for (int i = 0; i < Nn; i++) {
            const float4 a = ip[i * (Tt / 4) + idx];
            acc[64 + i] += dot4(a, a);
#pragma unroll
            for (int j = 0; j < Nn; j++)
                acc[i * 8 + j] += dot4(a, bv[j]);
        }
    }

    // Fixed-order reduction: warp shuffle then cross-warp via smem.
    __shared__ float sm[TPB / 32][NVALS];
    const int lane = tid & 31, warp = tid >> 5;
#pragma unroll
    for (int v = 0; v < NVALS; v++) {
        float x = acc[v];
#pragma unroll
        for (int off = 16; off; off >>= 1) x += __shfl_down_sync(0xffffffffu, x, off);
        if (lane == 0) sm[warp][v] = x;
    }
    __syncthreads();
    if (tid < NVALS) {
        float s = 0.f;
#pragma unroll
        for (int w = 0; w < TPB / 32; w++) s += sm[w][tid];
        g_partial[(b * NVALS + tid) * CPB + c] = s;   // [b][val][chunk]
    }
}

// ---------------------------------------------------------------------------
// Kernel 2: 512 threads. Phase A: each output is a contiguous 32-float
// (one 128B line) reduction via 8 float4 loads. Phase B: one warp per batch,
// linear-domain Sinkhorn entirely in registers + shuffles.
// ---------------------------------------------------------------------------
__global__ __launch_bounds__(512) void k_sink(float* __restrict__ out, int out_size) {
    __shared__ float G[Bb][NVALS];
    __shared__ float bloss[Bb];

    const int tid = threadIdx.x;

    // Phase A: 1280 outputs over 512 threads; contiguous reduction.
    for (int v = tid; v < Bb * NVALS; v += 512) {
        const float4* p = reinterpret_cast<const float4*>(&g_partial[v * CPB]);
        float s = 0.f;
#pragma unroll
        for (int q = 0; q < CPB / 4; q++) {
            const float4 x = p[q];
            s += x.x + x.y + x.z + x.w;
        }
        G[v / NVALS][v % NVALS] = s;
    }
    __syncthreads();

    // Phase B: warp w = batch w; lane layout (i0 = lane>>3 and i0+4) x (j = lane&7).
    const int w  = tid >> 5;
    const int l  = tid & 31;
    const int j  = l & 7;
    const int i0 = l >> 3;
    const int i1 = i0 + 4;
    const float invT = 1.0f / (float)Tt;

    if (w < Bb) {
        const float L0 = (G[w][64 + i0] + G[w][72 + j] - 2.f * G[w][i0 * 8 + j]) * invT;
        const float L1 = (G[w][64 + i1] + G[w][72 + j] - 2.f * G[w][i1 * 8 + j]) * invT;
        float p0 = __expf(-L0), p1 = __expf(-L1);   // P = exp(-COLDNESS*L)

        // Linear-domain Sinkhorn: column-normalize then row-normalize, 10x.
#pragma unroll
        for (int it = 0; it < 10; it++) {
            // column sums (over i): lanes {j, 8+j, 16+j, 24+j} x 2 regs
            float s = p0 + p1;
            s += __shfl_xor_sync(0xffffffffu, s, 8);
            s += __shfl_xor_sync(0xffffffffu, s, 16);
            const float r = __fdividef(1.f, s);
            p0 *= r;
            p1 *= r;

            // row sums (over j): 8 consecutive lanes, per register
            float s0 = p0, s1 = p1;
            s0 += __shfl_xor_sync(0xffffffffu, s0, 1);
            s1 += __shfl_xor_sync(0xffffffffu, s1, 1);
            s0 += __shfl_xor_sync(0xffffffffu, s0, 2);
            s1 += __shfl_xor_sync(0xffffffffu, s1, 2);
            s0 += __shfl_xor_sync(0xffffffffu, s0, 4);
            s1 += __shfl_xor_sync(0xffffffffu, s1, 4);
            p0 *= __fdividef(1.f, s0);
            p1 *= __fdividef(1.f, s1);
        }

        // Loss: (L + ln P) * P summed over the matrix, per batch.
        float lp = (L0 + __logf(p0)) * p0 + (L1 + __logf(p1)) * p1;
#pragma unroll
        for (int off = 16; off; off >>= 1) lp += __shfl_xor_sync(0xffffffffu, lp, off);
        if (l == 0) bloss[w] = lp;

        // Argmax over j per row, first occurrence on ties (matches jnp.argmax).
        float v0 = p0, v1 = p1;
        int   a0 = j,  a1 = j;
#pragma unroll
        for (int off = 1; off <= 4; off <<= 1) {
            float ov = __shfl_xor_sync(0xffffffffu, v0, off);
            int   oa = __shfl_xor_sync(0xffffffffu, a0, off);
            if (ov > v0 || (ov == v0 && oa < a0)) { v0 = ov; a0 = oa; }
            ov = __shfl_xor_sync(0xffffffffu, v1, off);
            oa = __shfl_xor_sync(0xffffffffu, a1, off);
            if (ov > v1 || (ov == v1 && oa < a1)) { v1 = ov; a1 = oa; }
        }
        if (out_size >= 1 + Bb * Nn && j == 0) {
            out[1 + w * Nn + i0] = (float)a0;
            out[1 + w * Nn + i1] = (float)a1;
        }
    }

    __syncthreads();
    if (tid == 0) {
        float s = 0.f;
#pragma unroll
        for (int b = 0; b < Bb; b++) s += bloss[b];
        out[0] = s * (1.0f / (float)Bb);
    }
}

// ---------------------------------------------------------------------------
extern "C" void kernel_launch(void* const* d_in, const int* in_sizes, int n_in,
                              void* d_out, int out_size) {
    const float* inp = (const float*)d_in[0];
    const float* tgt = (const float*)d_in[1];
    k_gram<<<GRID, TPB>>>(inp, tgt);
    k_sink<<<1, 512>>>((float*)d_out, out_size);
}

// round 5
// speedup vs baseline: 1.2490x; 1.0974x over previous
#include <cuda_runtime.h>
#include <cuda_bf16.h>

#define Bb   16
#define Nn   8
#define Tt   65536
#define CPB  32            // chunks per batch
#define TPB  128
#define NVALS 80           // 64 gram + 8 sum(x^2) + 8 sum(y^2)
#define ITERS ((Tt / CPB) / 4 / TPB)   // = 4 float4 iterations per thread
#define GRID (Bb * CPB)

// Partial sums laid out [batch][value][chunk] so k_sink reduces over a
// contiguous 128B line per output. No atomics anywhere -> deterministic.
__device__ float g_partial[Bb * NVALS * CPB];

__device__ __forceinline__ float dot4(float4 a, float4 b) {
    return a.x * b.x + a.y * b.y + a.z * b.z + a.w * b.w;
}

// ---------------------------------------------------------------------------
// Kernel 1: streaming Gram + self-norms.
//   * All 16 float4 loads issued back-to-back per iteration (MLP=16) — this
//     was R2's structure and measurably beats the low-MLP R4 restructure.
//   * __launch_bounds__(128, 3) -> 170-reg budget so the ~150 live values
//     (80 accumulators + 64 load regs) DON'T spill (R3's 142-reg allocation
//     spilled accumulators to local and tanked the loop).
// ---------------------------------------------------------------------------
__global__ __launch_bounds__(TPB, 3) void k_gram(const float* __restrict__ inp,
                                                 const float* __restrict__ tgt) {
    const int b   = blockIdx.x / CPB;
    const int c   = blockIdx.x % CPB;
    const int tid = threadIdx.x;

    const float4* ip = reinterpret_cast<const float4*>(inp) + (size_t)b * Nn * (Tt / 4);
    const float4* tp = reinterpret_cast<const float4*>(tgt) + (size_t)b * Nn * (Tt / 4);
    const int base = c * (Tt / CPB / 4) + tid;

    float acc[NVALS];
#pragma unroll
    for (int v = 0; v < NVALS; v++) acc[v] = 0.f;

#pragma unroll
    for (int k = 0; k < ITERS; k++) {
        const int idx = base + k * TPB;
        float4 av[Nn], bv[Nn];
#pragma unroll
        for (int i = 0; i < Nn; i++) av[i] = ip[i * (Tt / 4) + idx];
#pragma unroll
        for (int j = 0; j < Nn; j++) bv[j] = tp[j * (Tt / 4) + idx];
#pragma unroll
        for (int i = 0; i < Nn; i++) acc[64 + i] += dot4(av[i], av[i]);
#pragma unroll
        for (int j = 0; j < Nn; j++) acc[72 + j] += dot4(bv[j], bv[j]);
#pragma unroll
        for (int i = 0; i < Nn; i++)
#pragma unroll
            for (int j = 0; j < Nn; j++)
                acc[i * 8 + j] += dot4(av[i], bv[j]);
    }

    // Fixed-order reduction: warp shuffle then cross-warp via smem.
    __shared__ float sm[TPB / 32][NVALS];
    const int lane = tid & 31, warp = tid >> 5;
#pragma unroll
    for (int v = 0; v < NVALS; v++) {
        float x = acc[v];
#pragma unroll
        for (int off = 16; off; off >>= 1) x += __shfl_down_sync(0xffffffffu, x, off);
        if (lane == 0) sm[warp][v] = x;
    }
    __syncthreads();
    if (tid < NVALS) {
        float s = 0.f;
#pragma unroll
        for (int w = 0; w < TPB / 32; w++) s += sm[w][tid];
        g_partial[(b * NVALS + tid) * CPB + c] = s;   // [b][val][chunk]
    }
}

// ---------------------------------------------------------------------------
// Kernel 2: 512 threads. Phase A: each output is a contiguous 32-float
// (one 128B line) reduction via 8 float4 loads. Phase B: one warp per batch,
// linear-domain Sinkhorn entirely in registers + shuffles (no exp/log in
// the loop; P = exp(-L) is superbly conditioned, ~e^-2).
// ---------------------------------------------------------------------------
__global__ __launch_bounds__(512) void k_sink(float* __restrict__ out, int out_size) {
    __shared__ float G[Bb][NVALS];
    __shared__ float bloss[Bb];

    const int tid = threadIdx.x;

    // Phase A: 1280 outputs over 512 threads; contiguous reduction.
    for (int v = tid; v < Bb * NVALS; v += 512) {
        const float4* p = reinterpret_cast<const float4*>(&g_partial[v * CPB]);
        float s = 0.f;
#pragma unroll
        for (int q = 0; q < CPB / 4; q++) {
            const float4 x = p[q];
            s += x.x + x.y + x.z + x.w;
        }
        G[v / NVALS][v % NVALS] = s;
    }
    __syncthreads();

    // Phase B: warp w = batch w; lane layout (i0 = lane>>3 and i0+4) x (j = lane&7).
    const int w  = tid >> 5;
    const int l  = tid & 31;
    const int j  = l & 7;
    const int i0 = l >> 3;
    const int i1 = i0 + 4;
    const float invT = 1.0f / (float)Tt;

    if (w < Bb) {
        const float L0 = (G[w][64 + i0] + G[w][72 + j] - 2.f * G[w][i0 * 8 + j]) * invT;
        const float L1 = (G[w][64 + i1] + G[w][72 + j] - 2.f * G[w][i1 * 8 + j]) * invT;
        float p0 = __expf(-L0), p1 = __expf(-L1);   // P = exp(-COLDNESS*L)

        // Linear-domain Sinkhorn: column-normalize then row-normalize, 10x.
#pragma unroll
        for (int it = 0; it < 10; it++) {
            // column sums (over i): lanes {j, 8+j, 16+j, 24+j} x 2 regs
            float s = p0 + p1;
            s += __shfl_xor_sync(0xffffffffu, s, 8);
            s += __shfl_xor_sync(0xffffffffu, s, 16);
            const float r = __fdividef(1.f, s);
            p0 *= r;
            p1 *= r;

            // row sums (over j): 8 consecutive lanes, per register
            float s0 = p0, s1 = p1;
            s0 += __shfl_xor_sync(0xffffffffu, s0, 1);
            s1 += __shfl_xor_sync(0xffffffffu, s1, 1);
            s0 += __shfl_xor_sync(0xffffffffu, s0, 2);
            s1 += __shfl_xor_sync(0xffffffffu, s1, 2);
            s0 += __shfl_xor_sync(0xffffffffu, s0, 4);
            s1 += __shfl_xor_sync(0xffffffffu, s1, 4);
            p0 *= __fdividef(1.f, s0);
            p1 *= __fdividef(1.f, s1);
        }

        // Loss: (L + ln P) * P summed over the matrix, per batch.
        float lp = (L0 + __logf(p0)) * p0 + (L1 + __logf(p1)) * p1;
#pragma unroll
        for (int off = 16; off; off >>= 1) lp += __shfl_xor_sync(0xffffffffu, lp, off);
        if (l == 0) bloss[w] = lp;

        // Argmax over j per row, first occurrence on ties (matches jnp.argmax).
        float v0 = p0, v1 = p1;
        int   a0 = j,  a1 = j;
#pragma unroll
        for (int off = 1; off <= 4; off <<= 1) {
            float ov = __shfl_xor_sync(0xffffffffu, v0, off);
            int   oa = __shfl_xor_sync(0xffffffffu, a0, off);
            if (ov > v0 || (ov == v0 && oa < a0)) { v0 = ov; a0 = oa; }
            ov = __shfl_xor_sync(0xffffffffu, v1, off);
            oa = __shfl_xor_sync(0xffffffffu, a1, off);
            if (ov > v1 || (ov == v1 && oa < a1)) { v1 = ov; a1 = oa; }
        }
        if (out_size >= 1 + Bb * Nn && j == 0) {
            out[1 + w * Nn + i0] = (float)a0;
            out[1 + w * Nn + i1] = (float)a1;
        }
    }

    __syncthreads();
    if (tid == 0) {
        float s = 0.f;
#pragma unroll
        for (int b = 0; b < Bb; b++) s += bloss[b];
        out[0] = s * (1.0f / (float)Bb);
    }
}

// ---------------------------------------------------------------------------
extern "C" void kernel_launch(void* const* d_in, const int* in_sizes, int n_in,
                              void* d_out, int out_size) {
    const float* inp = (const float*)d_in[0];
    const float* tgt = (const float*)d_in[1];
    k_gram<<<GRID, TPB>>>(inp, tgt);
    k_sink<<<1, 512>>>((float*)d_out, out_size);
}